// round 3
// baseline (speedup 1.0000x reference)
#include <cuda_runtime.h>
#include <math.h>

#define DD 64
#define MAXN   50176            // padded node cap (>= N, mult of 256)
#define MAXNB  256
#define MAXNPAD (MAXNB * 256)
#define MAXR 256
#define MAXE 2097152

typedef unsigned long long ull;

// Scratch (static device globals — no allocation anywhere; BSS zero-initialized)
__device__ float g_X[2 * MAXN * DD];   // [0,N): nf@WI^T ; [N,2N): nf@WO^T
__device__ float g_R[2 * MAXR * DD];   // [0,R): r@WI^T-bI ; [256,256+R): r@WO^T-bO
__device__ int   g_cnt[MAXNPAD];       // per-dst degree (zero at entry, re-zeroed by gather)
__device__ int   g_lex[MAXNPAD];       // block-local exclusive scan
__device__ int   g_bsum[MAXNB];
__device__ int   g_base[MAXNB];
__device__ int   g_rank[MAXE];         // per-edge rank within its dst
__device__ unsigned g_pack[MAXE];      // packed (x_row | r_row<<17), CSR order

// ---------------------------------------------------------------------------
__device__ __forceinline__ ull pack2(float a, float b) {
    ull r;
    asm("mov.b64 %0, {%1, %2};" : "=l"(r) : "f"(a), "f"(b));
    return r;
}
__device__ __forceinline__ float2 unpack2(ull v) {
    float2 r;
    asm("mov.b64 {%0, %1}, %2;" : "=f"(r.x), "=f"(r.y) : "l"(v));
    return r;
}
__device__ __forceinline__ void ffma2(ull& d, ull a, ull b) {
    asm("fma.rn.f32x2 %0, %1, %2, %0;" : "+l"(d) : "l"(a), "l"(b));
}

// ---------------------------------------------------------------------------
// Fused: [relation tables + r_out] + [node transform via f32x2].
// Dynamic smem: swp (64*128 ull, duplicated W pairs) + sxT (64*64 f, k-major x)
// ---------------------------------------------------------------------------
#define FUSED_SMEM (64 * 128 * 8 + 64 * 64 * 4)

__global__ void __launch_bounds__(128) k_fused(
    const float* __restrict__ nf, const float* __restrict__ rf,
    const float* __restrict__ WI, const float* __restrict__ bI,
    const float* __restrict__ WO, const float* __restrict__ bO,
    const float* __restrict__ WR, const float* __restrict__ bR,
    float* __restrict__ r_out, int N, int R) {

    extern __shared__ __align__(16) unsigned char smem_raw[];
    ull*   swp = reinterpret_cast<ull*>(smem_raw);              // [k*128 + c]
    float* sxT = reinterpret_cast<float*>(smem_raw + 64 * 128 * 8); // [k*64 + r]

    int b = blockIdx.x;
    int tid = threadIdx.x;

    if (b < R) {
        // ---- relation tables ----
        int t = b, j = tid;
        if (j < DD) sxT[j] = rf[t * DD + j];
        __syncthreads();
        if (j < DD) {
            float aI = 0.f, aO = 0.f, aR = 0.f;
#pragma unroll 8
            for (int k = 0; k < DD; k++) {
                float v = sxT[k];
                aI += v * WI[j * DD + k];
                aO += v * WO[j * DD + k];
                aR += v * WR[j * DD + k];
            }
            g_R[t * DD + j]          = aI - bI[j];
            g_R[(MAXR + t) * DD + j] = aO - bO[j];
            r_out[t * DD + j]        = aR + bR[j];
        }
        return;
    }
    b -= R;

    int row0 = b * 64;

    // W duplicated pairs: swp[k*128 + c] = (w,w); c<64 -> WI col, else WO col-64
    for (int i = tid; i < 64 * 64; i += 128) {
        int j = i & 63, k = i >> 6;
        float wi = WI[j * 64 + k];
        float wo = WO[j * 64 + k];
        swp[k * 128 + j]      = pack2(wi, wi);
        swp[k * 128 + 64 + j] = pack2(wo, wo);
    }
    // x tile k-major
    for (int i = tid; i < 64 * 16; i += 128) {
        int r  = i >> 4;
        int c4 = (i & 15) * 4;
        float4 v = make_float4(0.f, 0.f, 0.f, 0.f);
        int row = row0 + r;
        if (row < N) v = *reinterpret_cast<const float4*>(nf + (size_t)row * 64 + c4);
        sxT[(c4 + 0) * 64 + r] = v.x;
        sxT[(c4 + 1) * 64 + r] = v.y;
        sxT[(c4 + 2) * 64 + r] = v.z;
        sxT[(c4 + 3) * 64 + r] = v.w;
    }
    __syncthreads();

    int trow = tid >> 4;      // 0..7
    int tcol = tid & 15;      // 0..15
    int r0 = trow * 8;

    ull acc2[4][8];
#pragma unroll
    for (int i = 0; i < 4; i++)
#pragma unroll
        for (int j = 0; j < 8; j++) acc2[i][j] = 0ULL;

#pragma unroll 4
    for (int k = 0; k < 64; k++) {
        ull a2[4], w2[8];
#pragma unroll
        for (int ii = 0; ii < 4; ii++)
            a2[ii] = *reinterpret_cast<const ull*>(&sxT[k * 64 + r0 + 2 * ii]);
#pragma unroll
        for (int jj = 0; jj < 8; jj++)
            w2[jj] = swp[k * 128 + tcol + 16 * jj];
#pragma unroll
        for (int ii = 0; ii < 4; ii++)
#pragma unroll
            for (int jj = 0; jj < 8; jj++) ffma2(acc2[ii][jj], a2[ii], w2[jj]);
    }

#pragma unroll
    for (int ii = 0; ii < 4; ii++) {
        int ra = row0 + r0 + 2 * ii;
#pragma unroll
        for (int jj = 0; jj < 8; jj++) {
            float2 p = unpack2(acc2[ii][jj]);
            int c = tcol + 16 * jj;
            size_t colBase = (c < 64) ? (size_t)c : (size_t)(c - 64);
            size_t rowAdd  = (c < 64) ? 0 : (size_t)N;
            if (ra < N)     g_X[(rowAdd + ra) * 64 + colBase]     = p.x;
            if (ra + 1 < N) g_X[(rowAdd + ra + 1) * 64 + colBase] = p.y;
        }
    }
}

// ---------------------------------------------------------------------------
// Histogram + rank (atomicAdd return)
// ---------------------------------------------------------------------------
__global__ void k_hist(const int* __restrict__ dst, int E) {
    int e = blockIdx.x * blockDim.x + threadIdx.x;
    if (e < E) g_rank[e] = atomicAdd(&g_cnt[dst[e]], 1);
}

// ---------------------------------------------------------------------------
// Two-level exclusive scan
// ---------------------------------------------------------------------------
__global__ void k_scanA() {
    __shared__ int s[256];
    int t = threadIdx.x;
    int i = blockIdx.x * 256 + t;
    int v = g_cnt[i];
    s[t] = v;
    __syncthreads();
#pragma unroll
    for (int off = 1; off < 256; off <<= 1) {
        int x = (t >= off) ? s[t - off] : 0;
        __syncthreads();
        s[t] += x;
        __syncthreads();
    }
    g_lex[i] = s[t] - v;
    if (t == 255) g_bsum[blockIdx.x] = s[t];
}

__global__ void k_scanB(int nb) {
    __shared__ int s[256];
    int t = threadIdx.x;
    int carry = 0;
    for (int c0 = 0; c0 < nb; c0 += 256) {
        int idx = c0 + t;
        int v = (idx < nb) ? g_bsum[idx] : 0;
        s[t] = v;
        __syncthreads();
#pragma unroll
        for (int off = 1; off < 256; off <<= 1) {
            int x = (t >= off) ? s[t - off] : 0;
            __syncthreads();
            s[t] += x;
            __syncthreads();
        }
        if (idx < nb) g_base[idx] = s[t] - v + carry;
        carry += s[255];
        __syncthreads();
    }
}

// ---------------------------------------------------------------------------
// Reorder (no atomics: rank precomputed by hist)
// ---------------------------------------------------------------------------
__global__ void k_reorder(const int* __restrict__ src, const int* __restrict__ dst,
                          const int* __restrict__ et, int E, int N,
                          const int* __restrict__ nrp, int halfFB) {
    int e = blockIdx.x * blockDim.x + threadIdx.x;
    if (e >= E) return;
    int half = nrp ? (nrp[0] >> 1) : halfFB;
    int d = dst[e];
    int s = src[e];
    int t = et[e];
    int pos = g_base[d >> 8] + g_lex[d] + g_rank[e];
    unsigned row, trow;
    if (t < half) { row = (unsigned)s;       trow = (unsigned)t; }
    else          { row = (unsigned)(s + N); trow = (unsigned)(t + MAXR); }
    g_pack[pos] = row | (trow << 17);
}

// ---------------------------------------------------------------------------
// Gather + mean: 1 warp/node, 2 edges per wave (half-warp x float4).
// X via __ldcg (bypass L1), R via default (L1-resident, ~100KB).
// Epilogue re-zeros g_cnt for the next invocation.
// ---------------------------------------------------------------------------
__global__ void __launch_bounds__(256) k_gather(float* __restrict__ out, int N) {
    int gid = blockIdx.x * 256 + threadIdx.x;
    int v = gid >> 5;
    if (v >= N) return;
    int lane = threadIdx.x & 31;
    int half = lane >> 4;
    int l16  = lane & 15;

    int start = g_base[v >> 8] + g_lex[v];
    int deg   = g_cnt[v];
    if (lane == 0) g_cnt[v] = 0;     // reset for next call (all lanes already read deg)

    const unsigned* __restrict__ pk = g_pack + start;
    const float4* __restrict__ X4 = reinterpret_cast<const float4*>(g_X);
    const float4* __restrict__ R4 = reinterpret_cast<const float4*>(g_R);

    float4 acc = make_float4(0.f, 0.f, 0.f, 0.f);
    int i = 0;
    for (; i + 8 <= deg; i += 8) {
#pragma unroll
        for (int u = 0; u < 4; u++) {
            unsigned p = pk[i + 2 * u + half];
            float4 x = __ldcg(&X4[(size_t)(p & 0x1FFFFu) * 16 + l16]);
            float4 r = R4[(size_t)(p >> 17) * 16 + l16];
            acc.x += x.x - r.x; acc.y += x.y - r.y;
            acc.z += x.z - r.z; acc.w += x.w - r.w;
        }
    }
    for (; i < deg; i += 2) {
        if (i + half < deg) {
            unsigned p = pk[i + half];
            float4 x = __ldcg(&X4[(size_t)(p & 0x1FFFFu) * 16 + l16]);
            float4 r = R4[(size_t)(p >> 17) * 16 + l16];
            acc.x += x.x - r.x; acc.y += x.y - r.y;
            acc.z += x.z - r.z; acc.w += x.w - r.w;
        }
    }
    // combine the two half-warps
    acc.x += __shfl_xor_sync(0xffffffffu, acc.x, 16);
    acc.y += __shfl_xor_sync(0xffffffffu, acc.y, 16);
    acc.z += __shfl_xor_sync(0xffffffffu, acc.z, 16);
    acc.w += __shfl_xor_sync(0xffffffffu, acc.w, 16);

    if (half == 0) {
        float inv = 1.0f / (float)(deg > 1 ? deg : 1);
        reinterpret_cast<float4*>(out)[(size_t)v * 16 + l16] =
            make_float4(acc.x * inv, acc.y * inv, acc.z * inv, acc.w * inv);
    }
}

// ---------------------------------------------------------------------------
extern "C" void kernel_launch(void* const* d_in, const int* in_sizes, int n_in,
                              void* d_out, int out_size) {
    const float* nf = (const float*)d_in[0];
    const float* rf = (const float*)d_in[1];
    const float* WI = (const float*)d_in[2];
    const float* bI = (const float*)d_in[3];
    const float* WO = (const float*)d_in[4];
    const float* bO = (const float*)d_in[5];
    const float* WR = (const float*)d_in[6];
    const float* bR = (const float*)d_in[7];
    const int* src  = (const int*)d_in[8];
    const int* dst  = (const int*)d_in[9];
    const int* et   = (const int*)d_in[10];
    const int* nrp  = (n_in > 11) ? (const int*)d_in[11] : nullptr;

    int Dv = in_sizes[3];            // = 64
    int N  = in_sizes[0] / Dv;
    int R  = in_sizes[1] / Dv;
    int E  = in_sizes[8];
    float* out = (float*)d_out;
    float* r_out = out + (size_t)N * Dv;

    int nb   = (N + 255) / 256;
    int nbNT = (N + 63) / 64;

    static_assert(FUSED_SMEM <= 96 * 1024, "smem budget");
    cudaFuncSetAttribute(k_fused, cudaFuncAttributeMaxDynamicSharedMemorySize,
                         FUSED_SMEM);

    // Fork: edge-index chain on a side stream, GEMM on the capture stream.
    cudaStream_t s2;
    cudaStreamCreateWithFlags(&s2, cudaStreamNonBlocking);
    cudaEvent_t eFork, eJoin;
    cudaEventCreateWithFlags(&eFork, cudaEventDisableTiming);
    cudaEventCreateWithFlags(&eJoin, cudaEventDisableTiming);

    cudaEventRecord(eFork, 0);
    cudaStreamWaitEvent(s2, eFork, 0);

    k_hist<<<(E + 255) / 256, 256, 0, s2>>>(dst, E);
    k_scanA<<<nb, 256, 0, s2>>>();
    k_scanB<<<1, 256, 0, s2>>>(nb);
    k_reorder<<<(E + 255) / 256, 256, 0, s2>>>(src, dst, et, E, N, nrp, R / 2);
    cudaEventRecord(eJoin, s2);

    k_fused<<<R + nbNT, 128, FUSED_SMEM>>>(nf, rf, WI, bI, WO, bO, WR, bR,
                                           r_out, N, R);

    cudaStreamWaitEvent(0, eJoin, 0);

    {
        long long threads = (long long)N * 32;
        k_gather<<<(int)((threads + 255) / 256), 256>>>(out, N);
    }
    // Streams/events intentionally not destroyed while capture may be active;
    // kernel_launch is invoked only a handful of times host-side.
}

// round 5
// speedup vs baseline: 1.2342x; 1.2342x over previous
#include <cuda_runtime.h>
#include <math.h>

#define DD 64
#define MAXN   50176
#define MAXNB  256
#define MAXNPAD (MAXNB * 256)
#define MAXR 256
#define MAXE 2097152

// Scratch (static device globals — no allocation anywhere; BSS zero-initialized)
__device__ float g_X[2 * MAXN * DD];   // [0,N): nf@WI^T ; [N,2N): nf@WO^T
__device__ float g_R[2 * MAXR * DD];   // [0,R): r@WI^T-bI ; [256,256+R): r@WO^T-bO
__device__ int   g_cnt[MAXNPAD];       // per-dst degree (zero at entry; gather re-zeros)
__device__ int   g_lex[MAXNPAD];       // block-local exclusive scan
__device__ int   g_bsum[MAXNB];
__device__ int   g_base[MAXNB];
__device__ int   g_rank[MAXE];         // per-edge rank within its dst
__device__ unsigned g_pack[MAXE];      // packed (x_row | r_row<<17), CSR order
__device__ int   g_scanDone;           // self-resetting completion counter

// ---------------------------------------------------------------------------
// K1: [histogram+rank] + [relation tables + r_out] + [node transform GEMM]
// dispatched by blockIdx range; 128 threads/block; 48KB static smem (GEMM only).
// ---------------------------------------------------------------------------
__global__ void __launch_bounds__(128) k_fused(
    const float* __restrict__ nf, const float* __restrict__ rf,
    const float* __restrict__ WI, const float* __restrict__ bI,
    const float* __restrict__ WO, const float* __restrict__ bO,
    const float* __restrict__ WR, const float* __restrict__ bR,
    float* __restrict__ r_out,
    const int* __restrict__ dst, int E,
    int N, int R, int nbH) {

    __shared__ float sx[64 * 64];
    __shared__ float sw[64 * 128];

    int b = blockIdx.x;
    int tid = threadIdx.x;

    if (b < nbH) {
        // ---- histogram + rank: 8 edges per thread ----
        int t0 = (b * 128 + tid) * 8;
        if (t0 + 8 <= E) {
            int4 d0 = *reinterpret_cast<const int4*>(dst + t0);
            int4 d1 = *reinterpret_cast<const int4*>(dst + t0 + 4);
            int r0 = atomicAdd(&g_cnt[d0.x], 1);
            int r1 = atomicAdd(&g_cnt[d0.y], 1);
            int r2 = atomicAdd(&g_cnt[d0.z], 1);
            int r3 = atomicAdd(&g_cnt[d0.w], 1);
            int r4 = atomicAdd(&g_cnt[d1.x], 1);
            int r5 = atomicAdd(&g_cnt[d1.y], 1);
            int r6 = atomicAdd(&g_cnt[d1.z], 1);
            int r7 = atomicAdd(&g_cnt[d1.w], 1);
            *reinterpret_cast<int4*>(g_rank + t0)     = make_int4(r0, r1, r2, r3);
            *reinterpret_cast<int4*>(g_rank + t0 + 4) = make_int4(r4, r5, r6, r7);
        } else {
            for (int e = t0; e < E; e++)
                g_rank[e] = atomicAdd(&g_cnt[dst[e]], 1);
        }
        return;
    }
    b -= nbH;

    if (b < R) {
        // ---- relation tables ----
        int t = b, j = tid;
        if (j < DD) sx[j] = rf[t * DD + j];
        __syncthreads();
        if (j < DD) {
            float aI = 0.f, aO = 0.f, aR = 0.f;
#pragma unroll 8
            for (int k = 0; k < DD; k++) {
                float v = sx[k];
                aI += v * WI[j * DD + k];
                aO += v * WO[j * DD + k];
                aR += v * WR[j * DD + k];
            }
            g_R[t * DD + j]          = aI - bI[j];
            g_R[(MAXR + t) * DD + j] = aO - bO[j];
            r_out[t * DD + j]        = aR + bR[j];
        }
        return;
    }
    b -= R;

    // ---- node transform: 64-row tile -> 128 cols (XA | XB) ----
    int row0 = b * 64;

    for (int i = tid; i < 64 * 64; i += 128) {
        int j = i & 63;
        int k = i >> 6;
        sw[k * 128 + j]      = WI[j * 64 + k];
        sw[k * 128 + 64 + j] = WO[j * 64 + k];
    }
    for (int i = tid; i < 64 * 16; i += 128) {
        int r  = i >> 4;
        int c4 = (i & 15) * 4;
        float4 v = make_float4(0.f, 0.f, 0.f, 0.f);
        int row = row0 + r;
        if (row < N) v = *reinterpret_cast<const float4*>(nf + (size_t)row * 64 + c4);
        sx[r * 64 + c4 + 0] = v.x;
        sx[r * 64 + c4 + 1] = v.y;
        sx[r * 64 + c4 + 2] = v.z;
        sx[r * 64 + c4 + 3] = v.w;
    }
    __syncthreads();

    int trow = tid >> 4;
    int tcol = tid & 15;
    int r0 = trow * 8;

    float acc[8][8];
#pragma unroll
    for (int i = 0; i < 8; i++)
#pragma unroll
        for (int j = 0; j < 8; j++) acc[i][j] = 0.f;

#pragma unroll 4
    for (int k = 0; k < 64; k++) {
        float a[8], w[8];
#pragma unroll
        for (int i = 0; i < 8; i++) a[i] = sx[(r0 + i) * 64 + k];
#pragma unroll
        for (int j = 0; j < 8; j++) w[j] = sw[k * 128 + tcol + 16 * j];
#pragma unroll
        for (int i = 0; i < 8; i++)
#pragma unroll
            for (int j = 0; j < 8; j++) acc[i][j] += a[i] * w[j];
    }

#pragma unroll
    for (int i = 0; i < 8; i++) {
        int row = row0 + r0 + i;
        if (row < N) {
#pragma unroll
            for (int j = 0; j < 8; j++) {
                int c = tcol + 16 * j;
                if (c < 64) g_X[(size_t)row * 64 + c]              = acc[i][j];
                else        g_X[(size_t)(N + row) * 64 + (c - 64)] = acc[i][j];
            }
        }
    }
}

// ---------------------------------------------------------------------------
// K2: fused two-level exclusive scan (last-arriving block scans block sums).
// ---------------------------------------------------------------------------
__global__ void k_scan(int nb) {
    __shared__ int s[256];
    __shared__ bool amLast;
    int t = threadIdx.x;
    int i = blockIdx.x * 256 + t;
    int v = g_cnt[i];
    s[t] = v;
    __syncthreads();
#pragma unroll
    for (int off = 1; off < 256; off <<= 1) {
        int x = (t >= off) ? s[t - off] : 0;
        __syncthreads();
        s[t] += x;
        __syncthreads();
    }
    g_lex[i] = s[t] - v;
    if (t == 255) g_bsum[blockIdx.x] = s[t];
    __threadfence();
    if (t == 0) {
        int d = atomicAdd(&g_scanDone, 1);
        amLast = (d == (int)gridDim.x - 1);
    }
    __syncthreads();
    if (amLast) {
        __threadfence();
        int v2 = (t < nb) ? g_bsum[t] : 0;
        s[t] = v2;
        __syncthreads();
#pragma unroll
        for (int off = 1; off < 256; off <<= 1) {
            int x = (t >= off) ? s[t - off] : 0;
            __syncthreads();
            s[t] += x;
            __syncthreads();
        }
        if (t < nb) g_base[t] = s[t] - v2;
        if (t == 0) g_scanDone = 0;     // reset for next graph replay
    }
}

// ---------------------------------------------------------------------------
// K3: reorder into CSR order, 4 edges/thread, branch pre-resolved into pack.
// ---------------------------------------------------------------------------
__device__ __forceinline__ void reorder_one(int s, int d, int t, int r,
                                            int N, int half) {
    int pos = g_base[d >> 8] + g_lex[d] + r;
    unsigned row, trow;
    if (t < half) { row = (unsigned)s;       trow = (unsigned)t; }
    else          { row = (unsigned)(s + N); trow = (unsigned)(t + MAXR); }
    g_pack[pos] = row | (trow << 17);
}

__global__ void k_reorder(const int* __restrict__ src, const int* __restrict__ dst,
                          const int* __restrict__ et, int E, int N,
                          const int* __restrict__ nrp, int halfFB) {
    int i = blockIdx.x * blockDim.x + threadIdx.x;
    int half = nrp ? (__ldg(nrp) >> 1) : halfFB;
    int main4 = E >> 2;
    if (i < main4) {
        int4 s4 = reinterpret_cast<const int4*>(src)[i];
        int4 d4 = reinterpret_cast<const int4*>(dst)[i];
        int4 t4 = reinterpret_cast<const int4*>(et)[i];
        int4 r4 = reinterpret_cast<const int4*>(g_rank)[i];
        reorder_one(s4.x, d4.x, t4.x, r4.x, N, half);
        reorder_one(s4.y, d4.y, t4.y, r4.y, N, half);
        reorder_one(s4.z, d4.z, t4.z, r4.z, N, half);
        reorder_one(s4.w, d4.w, t4.w, r4.w, N, half);
    } else if (i == main4) {
        for (int e = main4 * 4; e < E; e++)
            reorder_one(src[e], dst[e], et[e], g_rank[e], N, half);
    }
}

// ---------------------------------------------------------------------------
// K4: gather + mean. 1 warp/node, 2 edges per wave (half-warp x float4),
// unroll 4 (8 edges in flight). X via __ldcg (L2 only) so the 131KB R table
// stays L1-resident. Epilogue re-zeros g_cnt for the next replay.
// ---------------------------------------------------------------------------
__global__ void __launch_bounds__(256) k_gather(float* __restrict__ out, int N) {
    int gid = blockIdx.x * 256 + threadIdx.x;
    int v = gid >> 5;
    if (v >= N) return;
    int lane = threadIdx.x & 31;
    int half = lane >> 4;
    int l16  = lane & 15;

    int start = g_base[v >> 8] + g_lex[v];
    int deg   = g_cnt[v];

    const unsigned* __restrict__ pk = g_pack + start;
    const float4* __restrict__ X4 = reinterpret_cast<const float4*>(g_X);
    const float4* __restrict__ R4 = reinterpret_cast<const float4*>(g_R);

    float4 acc = make_float4(0.f, 0.f, 0.f, 0.f);
    int i = 0;
    for (; i + 8 <= deg; i += 8) {
#pragma unroll
        for (int u = 0; u < 4; u++) {
            unsigned p = pk[i + 2 * u + half];
            float4 x = __ldcg(&X4[(size_t)(p & 0x1FFFFu) * 16 + l16]);
            float4 r = R4[(size_t)(p >> 17) * 16 + l16];
            acc.x += x.x - r.x; acc.y += x.y - r.y;
            acc.z += x.z - r.z; acc.w += x.w - r.w;
        }
    }
    for (; i < deg; i += 2) {
        if (i + half < deg) {
            unsigned p = pk[i + half];
            float4 x = __ldcg(&X4[(size_t)(p & 0x1FFFFu) * 16 + l16]);
            float4 r = R4[(size_t)(p >> 17) * 16 + l16];
            acc.x += x.x - r.x; acc.y += x.y - r.y;
            acc.z += x.z - r.z; acc.w += x.w - r.w;
        }
    }
    acc.x += __shfl_xor_sync(0xffffffffu, acc.x, 16);
    acc.y += __shfl_xor_sync(0xffffffffu, acc.y, 16);
    acc.z += __shfl_xor_sync(0xffffffffu, acc.z, 16);
    acc.w += __shfl_xor_sync(0xffffffffu, acc.w, 16);

    if (half == 0) {
        float inv = 1.0f / (float)(deg > 1 ? deg : 1);
        reinterpret_cast<float4*>(out)[(size_t)v * 16 + l16] =
            make_float4(acc.x * inv, acc.y * inv, acc.z * inv, acc.w * inv);
    }
    if (lane == 0) g_cnt[v] = 0;    // reset for next replay (deg consumed above)
}

// ---------------------------------------------------------------------------
extern "C" void kernel_launch(void* const* d_in, const int* in_sizes, int n_in,
                              void* d_out, int out_size) {
    const float* nf = (const float*)d_in[0];
    const float* rf = (const float*)d_in[1];
    const float* WI = (const float*)d_in[2];
    const float* bI = (const float*)d_in[3];
    const float* WO = (const float*)d_in[4];
    const float* bO = (const float*)d_in[5];
    const float* WR = (const float*)d_in[6];
    const float* bR = (const float*)d_in[7];
    const int* src  = (const int*)d_in[8];
    const int* dst  = (const int*)d_in[9];
    const int* et   = (const int*)d_in[10];
    const int* nrp  = (n_in > 11) ? (const int*)d_in[11] : nullptr;

    int Dv = in_sizes[3];            // = 64
    int N  = in_sizes[0] / Dv;
    int R  = in_sizes[1] / Dv;
    int E  = in_sizes[8];
    float* out = (float*)d_out;
    float* r_out = out + (size_t)N * Dv;

    int nb   = (N + 255) / 256;      // scan blocks (<= 256)
    int nbNT = (N + 63) / 64;
    int nbH  = (E + 1023) / 1024;    // hist blocks: 128 thr x 8 edges

    // K1: hist + relation tables + node-transform GEMM (one kernel)
    k_fused<<<nbH + R + nbNT, 128>>>(nf, rf, WI, bI, WO, bO, WR, bR,
                                     r_out, dst, E, N, R, nbH);
    // K2: fused exclusive scan
    k_scan<<<nb, 256>>>(nb);
    // K3: CSR reorder
    {
        int work = (E >> 2) + 1;
        k_reorder<<<(work + 255) / 256, 256>>>(src, dst, et, E, N, nrp, R / 2);
    }
    // K4: gather + mean
    {
        long long threads = (long long)N * 32;
        k_gather<<<(int)((threads + 255) / 256), 256>>>(out, N);
    }
}

// round 6
// speedup vs baseline: 1.3064x; 1.0585x over previous
#include <cuda_runtime.h>
#include <cuda_fp16.h>
#include <math.h>

#define DD 64
#define MAXN   50176
#define MAXNB  256
#define MAXNPAD (MAXNB * 256)
#define MAXR 256
#define MAXE 2097152
#define SXP 65                       // padded x-tile row stride (bank-conflict fix)

typedef unsigned long long ull;

// Scratch (static device globals — no allocation anywhere; BSS zero-initialized)
__device__ unsigned g_Xh[2 * MAXN * 32];  // half2 words; row r = 32 half2 (64 cols)
__device__ unsigned g_Rh[2 * MAXR * 32];  // half2 words; [0,R)=RI, [256..)=RO
__device__ int   g_cnt[MAXNPAD];
__device__ int   g_lex[MAXNPAD];
__device__ int   g_bsum[MAXNB];
__device__ int   g_base[MAXNB];
__device__ int   g_rank[MAXE];
__device__ unsigned g_pack[MAXE];         // (x_row | r_row<<17), CSR order
__device__ int   g_scanDone;

__device__ __forceinline__ ull pack2(float a, float b) {
    ull r;
    asm("mov.b64 %0, {%1, %2};" : "=l"(r) : "f"(a), "f"(b));
    return r;
}
__device__ __forceinline__ float2 unpack2(ull v) {
    float2 r;
    asm("mov.b64 {%0, %1}, %2;" : "=f"(r.x), "=f"(r.y) : "l"(v));
    return r;
}
__device__ __forceinline__ void ffma2(ull& d, ull a, ull b) {
    asm("fma.rn.f32x2 %0, %1, %2, %0;" : "+l"(d) : "l"(a), "l"(b));
}

#define FSMEM (64 * 64 * 8 + 64 * SXP * 4)   // swp (32KB) + sx (16.6KB)

// ---------------------------------------------------------------------------
// K1: [histogram+rank] + [relation tables + r_out] + [node transform GEMM]
// ---------------------------------------------------------------------------
__global__ void __launch_bounds__(128) k_fused(
    const float* __restrict__ nf, const float* __restrict__ rf,
    const float* __restrict__ WI, const float* __restrict__ bI,
    const float* __restrict__ WO, const float* __restrict__ bO,
    const float* __restrict__ WR, const float* __restrict__ bR,
    float* __restrict__ r_out,
    const int* __restrict__ dst, int E,
    int N, int R, int nbH) {

    extern __shared__ __align__(16) unsigned char smem_raw[];
    ull*   swp = reinterpret_cast<ull*>(smem_raw);               // [k*64 + p] col-pairs
    float* sx  = reinterpret_cast<float*>(smem_raw + 64 * 64 * 8); // [r*SXP + k]

    int b = blockIdx.x;
    int tid = threadIdx.x;

    if (b < nbH) {
        // ---- histogram + rank: 8 edges per thread ----
        int t0 = (b * 128 + tid) * 8;
        if (t0 + 8 <= E) {
            int4 d0 = *reinterpret_cast<const int4*>(dst + t0);
            int4 d1 = *reinterpret_cast<const int4*>(dst + t0 + 4);
            int r0 = atomicAdd(&g_cnt[d0.x], 1);
            int r1 = atomicAdd(&g_cnt[d0.y], 1);
            int r2 = atomicAdd(&g_cnt[d0.z], 1);
            int r3 = atomicAdd(&g_cnt[d0.w], 1);
            int r4 = atomicAdd(&g_cnt[d1.x], 1);
            int r5 = atomicAdd(&g_cnt[d1.y], 1);
            int r6 = atomicAdd(&g_cnt[d1.z], 1);
            int r7 = atomicAdd(&g_cnt[d1.w], 1);
            *reinterpret_cast<int4*>(g_rank + t0)     = make_int4(r0, r1, r2, r3);
            *reinterpret_cast<int4*>(g_rank + t0 + 4) = make_int4(r4, r5, r6, r7);
        } else {
            for (int e = t0; e < E; e++)
                g_rank[e] = atomicAdd(&g_cnt[dst[e]], 1);
        }
        return;
    }
    b -= nbH;

    if (b < R) {
        // ---- relation tables (fp32 math, fp16 table store; r_out fp32) ----
        int t = b, j = tid;
        if (j < DD) sx[j] = rf[t * DD + j];
        __syncthreads();
        if (j < DD) {
            float aI = 0.f, aO = 0.f, aR = 0.f;
#pragma unroll 8
            for (int k = 0; k < DD; k++) {
                float v = sx[k];
                aI += v * WI[j * DD + k];
                aO += v * WO[j * DD + k];
                aR += v * WR[j * DD + k];
            }
            __half* Rh = reinterpret_cast<__half*>(g_Rh);
            Rh[t * DD + j]          = __float2half_rn(aI - bI[j]);
            Rh[(MAXR + t) * DD + j] = __float2half_rn(aO - bO[j]);
            r_out[t * DD + j]       = aR + bR[j];
        }
        return;
    }
    b -= R;

    // ---- node transform: 64-row tile -> 128 cols as 64 col-pairs (f32x2) ----
    int row0 = b * 64;

    // weight col-pairs: p<32 -> WI cols (2p,2p+1); p>=32 -> WO cols (2q,2q+1)
    for (int i = tid; i < 64 * 64; i += 128) {
        int p = i & 63;
        int k = i >> 6;
        float lo, hi;
        if (p < 32) { lo = WI[(2 * p) * 64 + k];       hi = WI[(2 * p + 1) * 64 + k]; }
        else { int q = p - 32; lo = WO[(2 * q) * 64 + k]; hi = WO[(2 * q + 1) * 64 + k]; }
        swp[k * 64 + p] = pack2(lo, hi);
    }
    // x tile, padded row stride SXP=65 (a-load conflict 8-way -> 2-way)
    for (int i = tid; i < 64 * 16; i += 128) {
        int r  = i >> 4;
        int c4 = (i & 15) * 4;
        float4 v = make_float4(0.f, 0.f, 0.f, 0.f);
        int row = row0 + r;
        if (row < N) v = *reinterpret_cast<const float4*>(nf + (size_t)row * 64 + c4);
        sx[r * SXP + c4 + 0] = v.x;
        sx[r * SXP + c4 + 1] = v.y;
        sx[r * SXP + c4 + 2] = v.z;
        sx[r * SXP + c4 + 3] = v.w;
    }
    __syncthreads();

    int trow = tid >> 4;
    int tcol = tid & 15;
    int r0 = trow * 8;

    ull acc2[8][4];
#pragma unroll
    for (int i = 0; i < 8; i++)
#pragma unroll
        for (int jj = 0; jj < 4; jj++) acc2[i][jj] = 0ULL;

#pragma unroll 4
    for (int k = 0; k < 64; k++) {
        ull w2[4], a2[8];
#pragma unroll
        for (int jj = 0; jj < 4; jj++) w2[jj] = swp[k * 64 + tcol + 16 * jj];
#pragma unroll
        for (int i = 0; i < 8; i++) {
            float a = sx[(r0 + i) * SXP + k];
            a2[i] = pack2(a, a);
        }
#pragma unroll
        for (int i = 0; i < 8; i++)
#pragma unroll
            for (int jj = 0; jj < 4; jj++) ffma2(acc2[i][jj], a2[i], w2[jj]);
    }

#pragma unroll
    for (int i = 0; i < 8; i++) {
        int row = row0 + r0 + i;
        if (row < N) {
#pragma unroll
            for (int jj = 0; jj < 4; jj++) {
                int p = tcol + 16 * jj;
                float2 f = unpack2(acc2[i][jj]);
                __half2 h = __floats2half2_rn(f.x, f.y);
                unsigned hv = *reinterpret_cast<unsigned*>(&h);
                if (p < 32) g_Xh[(size_t)row * 32 + p]            = hv;
                else        g_Xh[(size_t)(N + row) * 32 + (p - 32)] = hv;
            }
        }
    }
}

// ---------------------------------------------------------------------------
// K2: fused two-level exclusive scan (last-arriving block scans block sums).
// ---------------------------------------------------------------------------
__global__ void k_scan(int nb) {
    __shared__ int s[256];
    __shared__ bool amLast;
    int t = threadIdx.x;
    int i = blockIdx.x * 256 + t;
    int v = g_cnt[i];
    s[t] = v;
    __syncthreads();
#pragma unroll
    for (int off = 1; off < 256; off <<= 1) {
        int x = (t >= off) ? s[t - off] : 0;
        __syncthreads();
        s[t] += x;
        __syncthreads();
    }
    g_lex[i] = s[t] - v;
    if (t == 255) g_bsum[blockIdx.x] = s[t];
    __threadfence();
    if (t == 0) {
        int d = atomicAdd(&g_scanDone, 1);
        amLast = (d == (int)gridDim.x - 1);
    }
    __syncthreads();
    if (amLast) {
        __threadfence();
        int v2 = (t < nb) ? g_bsum[t] : 0;
        s[t] = v2;
        __syncthreads();
#pragma unroll
        for (int off = 1; off < 256; off <<= 1) {
            int x = (t >= off) ? s[t - off] : 0;
            __syncthreads();
            s[t] += x;
            __syncthreads();
        }
        if (t < nb) g_base[t] = s[t] - v2;
        if (t == 0) g_scanDone = 0;
    }
}

// ---------------------------------------------------------------------------
// K3: reorder into CSR order, 4 edges/thread, branch pre-resolved into pack.
// ---------------------------------------------------------------------------
__device__ __forceinline__ void reorder_one(int s, int d, int t, int r,
                                            int N, int half) {
    int pos = g_base[d >> 8] + g_lex[d] + r;
    unsigned row, trow;
    if (t < half) { row = (unsigned)s;       trow = (unsigned)t; }
    else          { row = (unsigned)(s + N); trow = (unsigned)(t + MAXR); }
    g_pack[pos] = row | (trow << 17);
}

__global__ void k_reorder(const int* __restrict__ src, const int* __restrict__ dst,
                          const int* __restrict__ et, int E, int N,
                          const int* __restrict__ nrp, int halfFB) {
    int i = blockIdx.x * blockDim.x + threadIdx.x;
    int half = nrp ? (__ldg(nrp) >> 1) : halfFB;
    int main4 = E >> 2;
    if (i < main4) {
        int4 s4 = reinterpret_cast<const int4*>(src)[i];
        int4 d4 = reinterpret_cast<const int4*>(dst)[i];
        int4 t4 = reinterpret_cast<const int4*>(et)[i];
        int4 r4 = reinterpret_cast<const int4*>(g_rank)[i];
        reorder_one(s4.x, d4.x, t4.x, r4.x, N, half);
        reorder_one(s4.y, d4.y, t4.y, r4.y, N, half);
        reorder_one(s4.z, d4.z, t4.z, r4.z, N, half);
        reorder_one(s4.w, d4.w, t4.w, r4.w, N, half);
    } else if (i == main4) {
        for (int e = main4 * 4; e < E; e++)
            reorder_one(src[e], dst[e], et[e], g_rank[e], N, half);
    }
}

// ---------------------------------------------------------------------------
// K4: gather + mean. 1 warp/node, 2 edges per wave (half-warp x uint2 fp16),
// unroll 4. X via __ldcg so the 128KB fp16 R table stays L1-resident.
// fp32 accumulate. Epilogue re-zeros g_cnt for the next replay.
// ---------------------------------------------------------------------------
__global__ void __launch_bounds__(256) k_gather(float* __restrict__ out, int N) {
    int gid = blockIdx.x * 256 + threadIdx.x;
    int v = gid >> 5;
    if (v >= N) return;
    int lane = threadIdx.x & 31;
    int half = lane >> 4;
    int l16  = lane & 15;

    int start = g_base[v >> 8] + g_lex[v];
    int deg   = g_cnt[v];

    const unsigned* __restrict__ pk = g_pack + start;
    const uint2* __restrict__ X2 = reinterpret_cast<const uint2*>(g_Xh);
    const uint2* __restrict__ R2 = reinterpret_cast<const uint2*>(g_Rh);

    float4 acc = make_float4(0.f, 0.f, 0.f, 0.f);
    int i = 0;
    for (; i + 8 <= deg; i += 8) {
#pragma unroll
        for (int u = 0; u < 4; u++) {
            unsigned p = pk[i + 2 * u + half];
            uint2 x = __ldcg(&X2[(size_t)(p & 0x1FFFFu) * 16 + l16]);
            uint2 r = R2[(size_t)(p >> 17) * 16 + l16];
            float2 xa = __half22float2(*reinterpret_cast<const __half2*>(&x.x));
            float2 xb = __half22float2(*reinterpret_cast<const __half2*>(&x.y));
            float2 ra = __half22float2(*reinterpret_cast<const __half2*>(&r.x));
            float2 rb = __half22float2(*reinterpret_cast<const __half2*>(&r.y));
            acc.x += xa.x - ra.x; acc.y += xa.y - ra.y;
            acc.z += xb.x - rb.x; acc.w += xb.y - rb.y;
        }
    }
    for (; i < deg; i += 2) {
        if (i + half < deg) {
            unsigned p = pk[i + half];
            uint2 x = __ldcg(&X2[(size_t)(p & 0x1FFFFu) * 16 + l16]);
            uint2 r = R2[(size_t)(p >> 17) * 16 + l16];
            float2 xa = __half22float2(*reinterpret_cast<const __half2*>(&x.x));
            float2 xb = __half22float2(*reinterpret_cast<const __half2*>(&x.y));
            float2 ra = __half22float2(*reinterpret_cast<const __half2*>(&r.x));
            float2 rb = __half22float2(*reinterpret_cast<const __half2*>(&r.y));
            acc.x += xa.x - ra.x; acc.y += xa.y - ra.y;
            acc.z += xb.x - rb.x; acc.w += xb.y - rb.y;
        }
    }
    acc.x += __shfl_xor_sync(0xffffffffu, acc.x, 16);
    acc.y += __shfl_xor_sync(0xffffffffu, acc.y, 16);
    acc.z += __shfl_xor_sync(0xffffffffu, acc.z, 16);
    acc.w += __shfl_xor_sync(0xffffffffu, acc.w, 16);

    if (half == 0) {
        float inv = 1.0f / (float)(deg > 1 ? deg : 1);
        reinterpret_cast<float4*>(out)[(size_t)v * 16 + l16] =
            make_float4(acc.x * inv, acc.y * inv, acc.z * inv, acc.w * inv);
    }
    if (lane == 0) g_cnt[v] = 0;
}

// ---------------------------------------------------------------------------
extern "C" void kernel_launch(void* const* d_in, const int* in_sizes, int n_in,
                              void* d_out, int out_size) {
    const float* nf = (const float*)d_in[0];
    const float* rf = (const float*)d_in[1];
    const float* WI = (const float*)d_in[2];
    const float* bI = (const float*)d_in[3];
    const float* WO = (const float*)d_in[4];
    const float* bO = (const float*)d_in[5];
    const float* WR = (const float*)d_in[6];
    const float* bR = (const float*)d_in[7];
    const int* src  = (const int*)d_in[8];
    const int* dst  = (const int*)d_in[9];
    const int* et   = (const int*)d_in[10];
    const int* nrp  = (n_in > 11) ? (const int*)d_in[11] : nullptr;

    int Dv = in_sizes[3];            // = 64
    int N  = in_sizes[0] / Dv;
    int R  = in_sizes[1] / Dv;
    int E  = in_sizes[8];
    float* out = (float*)d_out;
    float* r_out = out + (size_t)N * Dv;

    int nb   = (N + 255) / 256;
    int nbNT = (N + 63) / 64;
    int nbH  = (E + 1023) / 1024;

    static int attrSet = 0;
    if (!attrSet) {
        cudaFuncSetAttribute(k_fused, cudaFuncAttributeMaxDynamicSharedMemorySize,
                             FSMEM);
        attrSet = 1;
    }

    k_fused<<<nbH + R + nbNT, 128, FSMEM>>>(nf, rf, WI, bI, WO, bO, WR, bR,
                                            r_out, dst, E, N, R, nbH);
    k_scan<<<nb, 256>>>(nb);
    {
        int work = (E >> 2) + 1;
        k_reorder<<<(work + 255) / 256, 256>>>(src, dst, et, E, N, nrp, R / 2);
    }
    {
        long long threads = (long long)N * 32;
        k_gather<<<(int)((threads + 255) / 256), 256>>>(out, N);
    }
}